// round 5
// baseline (speedup 1.0000x reference)
#include <cuda_runtime.h>
#include <math.h>
#include <stdint.h>

#define TL 50
#define TD 200
#define NBLK 3
#define NTHREADS 512
#define WS 204           // padded row stride for work buffers
#define SSTRIDE 52       // padded row stride for scores
#define NEGV (-4294967296.0f)   // float32(-2^32+1)
#define LNEPS 1e-8f

__device__ __forceinline__ float wsum(float v) {
#pragma unroll
    for (int o = 16; o > 0; o >>= 1) v += __shfl_xor_sync(0xffffffffu, v, o);
    return v;
}
__device__ __forceinline__ float wmax(float v) {
#pragma unroll
    for (int o = 16; o > 0; o >>= 1) v = fmaxf(v, __shfl_xor_sync(0xffffffffu, v, o));
    return v;
}

// ---- packed fp32x2 helpers (Blackwell FFMA2) ----
__device__ __forceinline__ void ffma2(uint64_t& acc, uint64_t a, uint64_t b) {
    asm("fma.rn.f32x2 %0, %1, %2, %0;" : "+l"(acc) : "l"(a), "l"(b));
}
__device__ __forceinline__ uint64_t rep2(float x) {
    uint64_t r;
    asm("mov.b64 %0, {%1, %1};" : "=l"(r) : "f"(x));
    return r;
}
__device__ __forceinline__ uint64_t pack2(float lo, float hi) {
    uint64_t r;
    asm("mov.b64 %0, {%1, %2};" : "=l"(r) : "f"(lo), "f"(hi));
    return r;
}
__device__ __forceinline__ void unpack2(uint64_t v, float& lo, float& hi) {
    asm("mov.b64 {%0, %1}, %2;" : "=f"(lo), "=f"(hi) : "l"(v));
}

// Core FFMA2 block for one k4 step over 10 m-rows
__device__ __forceinline__ void fma_block10(
    uint64_t acc[10][2], const float4 w[4],
    const float* __restrict__ X, int xs, int m0, int k)
{
    const uint64_t wa0 = pack2(w[0].x, w[0].y), wb0 = pack2(w[0].z, w[0].w);
    const uint64_t wa1 = pack2(w[1].x, w[1].y), wb1 = pack2(w[1].z, w[1].w);
    const uint64_t wa2 = pack2(w[2].x, w[2].y), wb2 = pack2(w[2].z, w[2].w);
    const uint64_t wa3 = pack2(w[3].x, w[3].y), wb3 = pack2(w[3].z, w[3].w);
#pragma unroll
    for (int i = 0; i < 10; i++) {
        const float4 xv = *(const float4*)(X + (m0 + i) * xs + k);
        const uint64_t x0 = rep2(xv.x);
        ffma2(acc[i][0], x0, wa0);
        ffma2(acc[i][1], x0, wb0);
        const uint64_t x1 = rep2(xv.y);
        ffma2(acc[i][0], x1, wa1);
        ffma2(acc[i][1], x1, wb1);
        const uint64_t x2 = rep2(xv.z);
        ffma2(acc[i][0], x2, wa2);
        ffma2(acc[i][1], x2, wb2);
        const uint64_t x3 = rep2(xv.w);
        ffma2(acc[i][0], x3, wa3);
        ffma2(acc[i][1], x3, wb3);
    }
}

// ---- full GEMM: OUT = act(X @ W + bias), 250 threads, 10m x 4n, W double-buffered ----
template<bool RELU>
__device__ __forceinline__ void gemm_full(
    const float* __restrict__ X, int xs,
    const float* __restrict__ W,
    const float* __restrict__ bias,
    float* __restrict__ OUT, int t)
{
    if (t < 250) {
        const int cg = t % 50, rg = t / 50;
        const int n0 = cg * 4, m0 = rg * 10;
        uint64_t acc[10][2];
#pragma unroll
        for (int i = 0; i < 10; i++) { acc[i][0] = 0ull; acc[i][1] = 0ull; }

        const float* Wp = W + n0;
        float4 wbuf[2][4];
#pragma unroll
        for (int r = 0; r < 4; r++)
            wbuf[0][r] = __ldg((const float4*)(Wp + r * TD));

#pragma unroll 2
        for (int k4 = 0; k4 < TD / 4; k4++) {
            const int cur = k4 & 1;
            if (k4 < TD / 4 - 1) {
#pragma unroll
                for (int r = 0; r < 4; r++)
                    wbuf[cur ^ 1][r] =
                        __ldg((const float4*)(Wp + (4 * (k4 + 1) + r) * TD));
            }
            fma_block10(acc, wbuf[cur], X, xs, m0, 4 * k4);
        }

        const float4 bvv = __ldg((const float4*)(bias + n0));
#pragma unroll
        for (int i = 0; i < 10; i++) {
            float a0, a1, a2, a3;
            unpack2(acc[i][0], a0, a1);
            unpack2(acc[i][1], a2, a3);
            a0 += bvv.x; a1 += bvv.y; a2 += bvv.z; a3 += bvv.w;
            if (RELU) {
                a0 = fmaxf(a0, 0.0f); a1 = fmaxf(a1, 0.0f);
                a2 = fmaxf(a2, 0.0f); a3 = fmaxf(a3, 0.0f);
            }
            float* o = OUT + (m0 + i) * WS + n0;
            o[0] = a0; o[1] = a1; o[2] = a2; o[3] = a3;
        }
    }
}

// ---- partial GEMM: OUT = X[:, k0:k0+100] @ W[k0:k0+100, :] (raw), double-buffered ----
__device__ __forceinline__ void gemm_part(
    const float* __restrict__ X, int xs,
    const float* __restrict__ W,
    float* __restrict__ OUT, int t, int k0)
{
    if (t < 250) {
        const int cg = t % 50, rg = t / 50;
        const int n0 = cg * 4, m0 = rg * 10;
        uint64_t acc[10][2];
#pragma unroll
        for (int i = 0; i < 10; i++) { acc[i][0] = 0ull; acc[i][1] = 0ull; }

        const float* Wp = W + n0;
        float4 wbuf[2][4];
#pragma unroll
        for (int r = 0; r < 4; r++)
            wbuf[0][r] = __ldg((const float4*)(Wp + (k0 + r) * TD));

#pragma unroll 2
        for (int k4 = 0; k4 < TD / 8; k4++) {
            const int cur = k4 & 1;
            if (k4 < TD / 8 - 1) {
#pragma unroll
                for (int r = 0; r < 4; r++)
                    wbuf[cur ^ 1][r] =
                        __ldg((const float4*)(Wp + (k0 + 4 * (k4 + 1) + r) * TD));
            }
            fma_block10(acc, wbuf[cur], X, xs, m0, k0 + 4 * k4);
        }

#pragma unroll
        for (int i = 0; i < 10; i++) {
            float a0, a1, a2, a3;
            unpack2(acc[i][0], a0, a1);
            unpack2(acc[i][1], a2, a3);
            float* o = OUT + (m0 + i) * WS + n0;
            o[0] = a0; o[1] = a1; o[2] = a2; o[3] = a3;
        }
    }
}

__global__ void __launch_bounds__(NTHREADS, 1) encoder_kernel(
    const int* __restrict__ tokens, const float* __restrict__ emb,
    const float* __restrict__ Wq, const float* __restrict__ bq,
    const float* __restrict__ Wk, const float* __restrict__ bk,
    const float* __restrict__ Wv, const float* __restrict__ bv,
    const float* __restrict__ W1, const float* __restrict__ b1,
    const float* __restrict__ W2, const float* __restrict__ b2,
    const float* __restrict__ lng, const float* __restrict__ lnb,
    float* __restrict__ out)
{
    extern __shared__ float sm[];
    float* sx   = sm;                     // 50*200
    float* bufA = sx + TL * TD;           // 50*204
    float* bufB = bufA + TL * WS;         // 50*204
    float* bufV = bufB + TL * WS;         // 50*204
    float* sS   = bufV + TL * WS;         // 50*52
    float* km   = sS + TL * SSTRIDE;      // 50  (1.0 if key row masked)

    const int tid = threadIdx.x;
    const int b = blockIdx.x;
    const int warp = tid >> 5, lane = tid & 31;

    // Embedding gather: sx = emb[tokens[b]]
    {
        const int* tok = tokens + b * TL;
        for (int idx = tid; idx < TL * TD / 4; idx += NTHREADS) {
            const int m = idx / (TD / 4);
            const int c = idx - m * (TD / 4);
            const int t = __ldg(tok + m);
            ((float4*)sx)[idx] = __ldg((const float4*)emb + (size_t)t * (TD / 4) + c);
        }
    }

    for (int blk = 0; blk < NBLK; blk++) {
        const float* wq = Wq + blk * TD * TD;
        const float* wk = Wk + blk * TD * TD;
        const float* wv = Wv + blk * TD * TD;
        const float* w1 = W1 + blk * TD * TD;
        const float* w2 = W2 + blk * TD * TD;
        const float* bq_ = bq + blk * TD;
        const float* bk_ = bk + blk * TD;
        const float* bv_ = bv + blk * TD;
        const float* b1_ = b1 + blk * TD;
        const float* b2_ = b2 + blk * TD;
        const float* g_  = lng + blk * TD;
        const float* be_ = lnb + blk * TD;

        __syncthreads();   // sx ready (gather or previous LN)

        // Row masks: km[r] = 1 if sum(x[r,:]) == 0
        for (int r = warp; r < TL; r += NTHREADS / 32) {
            float s = 0.0f;
            for (int c = lane; c < TD; c += 32) s += sx[r * TD + c];
            s = wsum(s);
            if (lane == 0) km[r] = (s == 0.0f) ? 1.0f : 0.0f;
        }

        // Q (group 0) || K (group 1)
        if (tid < 256) gemm_full<true>(sx, TD, wq, bq_, bufA, tid);
        else           gemm_full<true>(sx, TD, wk, bk_, bufB, tid - 256);
        __syncthreads();

        // scores (group 0, 250 thr) || V (group 1)
        if (tid < 256) {
            if (tid < 250) {
                const int q = tid / 5;
                const int kk0 = (tid % 5) * 10;
                uint64_t acc[10];
#pragma unroll
                for (int j = 0; j < 10; j++) acc[j] = 0ull;
#pragma unroll 2
                for (int d = 0; d < TD; d += 4) {
                    const float4 qa = *(const float4*)(bufA + q * WS + d);
                    const uint64_t q01 = pack2(qa.x, qa.y);
                    const uint64_t q23 = pack2(qa.z, qa.w);
#pragma unroll
                    for (int j = 0; j < 10; j++) {
                        const float4 kv = *(const float4*)(bufB + (kk0 + j) * WS + d);
                        ffma2(acc[j], q01, pack2(kv.x, kv.y));
                        ffma2(acc[j], q23, pack2(kv.z, kv.w));
                    }
                }
                const float scale = 0.07071067811865475f;  // 1/sqrt(200)
#pragma unroll
                for (int j = 0; j < 10; j++) {
                    float lo, hi;
                    unpack2(acc[j], lo, hi);
                    sS[q * SSTRIDE + kk0 + j] =
                        (km[kk0 + j] != 0.0f) ? NEGV : (lo + hi) * scale;
                }
            }
        } else {
            gemm_full<true>(sx, TD, wv, bv_, bufV, tid - 256);
        }
        __syncthreads();

        // Softmax over rows of sS, then * query mask
        for (int q = warp; q < TL; q += NTHREADS / 32) {
            const float a  = sS[q * SSTRIDE + lane];
            const float bb = (lane < TL - 32) ? sS[q * SSTRIDE + 32 + lane] : -3.4e38f;
            const float mx = wmax(fmaxf(a, bb));
            const float ea = expf(a - mx);
            const float eb = (lane < TL - 32) ? expf(bb - mx) : 0.0f;
            const float ssum = wsum(ea + eb);
            const float fac = (1.0f - km[q]) / ssum;
            sS[q * SSTRIDE + lane] = ea * fac;
            if (lane < TL - 32) sS[q * SSTRIDE + 32 + lane] = eb * fac;
        }
        __syncthreads();

        // x += attn @ V   (500 threads, n-packed FFMA2)
        if (tid < 500) {
            const int cg = tid % 50, rg = tid / 50;
            const int n0 = cg * 4, m0 = rg * 5;
            uint64_t acc[5][2];
#pragma unroll
            for (int i = 0; i < 5; i++) { acc[i][0] = 0ull; acc[i][1] = 0ull; }
#pragma unroll 2
            for (int kk = 0; kk < TL; kk++) {
                const float4 v = *(const float4*)(bufV + kk * WS + n0);
                const uint64_t v01 = pack2(v.x, v.y);
                const uint64_t v23 = pack2(v.z, v.w);
#pragma unroll
                for (int i = 0; i < 5; i++) {
                    const uint64_t a = rep2(sS[(m0 + i) * SSTRIDE + kk]);
                    ffma2(acc[i][0], a, v01);
                    ffma2(acc[i][1], a, v23);
                }
            }
#pragma unroll
            for (int i = 0; i < 5; i++) {
                float a0, a1, a2, a3;
                unpack2(acc[i][0], a0, a1);
                unpack2(acc[i][1], a2, a3);
                float* o = sx + (m0 + i) * TD + n0;
                o[0] += a0; o[1] += a1; o[2] += a2; o[3] += a3;
            }
        }
        __syncthreads();

        // FFN1 k-split: group0 k=[0,100) -> bufA, group1 k=[100,200) -> bufB
        if (tid < 256) gemm_part(sx, TD, w1, bufA, tid, 0);
        else           gemm_part(sx, TD, w1, bufB, tid - 256, TD / 2);
        __syncthreads();

        // merge: bufA = relu(bufA + bufB + b1)
        for (int idx = tid; idx < TL * TD / 4; idx += NTHREADS) {
            const int r = idx / (TD / 4), c4 = idx % (TD / 4);
            float4 a = ((const float4*)(bufA + r * WS))[c4];
            float4 p = ((const float4*)(bufB + r * WS))[c4];
            const float4 bb = __ldg((const float4*)b1_ + c4);
            a.x = fmaxf(a.x + p.x + bb.x, 0.0f);
            a.y = fmaxf(a.y + p.y + bb.y, 0.0f);
            a.z = fmaxf(a.z + p.z + bb.z, 0.0f);
            a.w = fmaxf(a.w + p.w + bb.w, 0.0f);
            ((float4*)(bufA + r * WS))[c4] = a;
        }
        __syncthreads();

        // FFN2 k-split: group0 k=[0,100) -> bufB, group1 k=[100,200) -> bufV
        if (tid < 256) gemm_part(bufA, WS, w2, bufB, tid, 0);
        else           gemm_part(bufA, WS, w2, bufV, tid - 256, TD / 2);
        __syncthreads();

        // LayerNorm( bufB + bufV + b2 ) * g + be, residual into sx
        for (int r = warp; r < TL; r += NTHREADS / 32) {
            float hbuf[7];
            int nc = 0;
            float s = 0.0f;
            for (int c = lane; c < TD; c += 32) {
                const float h = bufB[r * WS + c] + bufV[r * WS + c] + __ldg(b2_ + c);
                hbuf[nc++] = h;
                s += h;
            }
            s = wsum(s);
            const float mu = s * (1.0f / TD);
            float v = 0.0f;
            for (int i = 0; i < nc; i++) {
                const float dd = hbuf[i] - mu;
                v = fmaf(dd, dd, v);
            }
            v = wsum(v);
            const float inv = rsqrtf(v * (1.0f / TD) + LNEPS);
            nc = 0;
            for (int c = lane; c < TD; c += 32) {
                const float y = (hbuf[nc++] - mu) * inv * __ldg(g_ + c) + __ldg(be_ + c);
                sx[r * TD + c] += y;
            }
        }
    }
    __syncthreads();

    // Write out
    {
        float4* o = (float4*)(out + (size_t)b * TL * TD);
        for (int idx = tid; idx < TL * TD / 4; idx += NTHREADS)
            o[idx] = ((const float4*)sx)[idx];
    }
}

extern "C" void kernel_launch(void* const* d_in, const int* in_sizes, int n_in,
                              void* d_out, int out_size) {
    const int*   tokens = (const int*)d_in[0];
    const float* emb = (const float*)d_in[1];
    const float* Wq  = (const float*)d_in[2];
    const float* bq  = (const float*)d_in[3];
    const float* Wk  = (const float*)d_in[4];
    const float* bk  = (const float*)d_in[5];
    const float* Wv  = (const float*)d_in[6];
    const float* bv  = (const float*)d_in[7];
    const float* W1  = (const float*)d_in[8];
    const float* b1  = (const float*)d_in[9];
    const float* W2  = (const float*)d_in[10];
    const float* b2  = (const float*)d_in[11];
    const float* lng = (const float*)d_in[12];
    const float* lnb = (const float*)d_in[13];
    float* out = (float*)d_out;

    const int B = in_sizes[0] / TL;
    const size_t smem = (size_t)(TL * TD + 3 * TL * WS + TL * SSTRIDE + TL) * sizeof(float);

    cudaFuncSetAttribute(encoder_kernel,
                         cudaFuncAttributeMaxDynamicSharedMemorySize, (int)smem);
    encoder_kernel<<<B, NTHREADS, smem>>>(tokens, emb, Wq, bq, Wk, bk, Wv, bv,
                                          W1, b1, W2, b2, lng, lnb, out);
}

// round 6
// speedup vs baseline: 1.0896x; 1.0896x over previous
#include <cuda_runtime.h>
#include <math.h>
#include <stdint.h>

#define TL 50
#define TD 200
#define NBLK 3
#define NTHREADS 512
#define WS 204           // padded row stride for work buffers
#define SSTRIDE 52       // padded row stride for scores
#define NEGV (-4294967296.0f)   // float32(-2^32+1)
#define LNEPS 1e-8f

__device__ __forceinline__ float wsum(float v) {
#pragma unroll
    for (int o = 16; o > 0; o >>= 1) v += __shfl_xor_sync(0xffffffffu, v, o);
    return v;
}
__device__ __forceinline__ float wmax(float v) {
#pragma unroll
    for (int o = 16; o > 0; o >>= 1) v = fmaxf(v, __shfl_xor_sync(0xffffffffu, v, o));
    return v;
}

// ---- packed fp32x2 helpers (Blackwell FFMA2) ----
__device__ __forceinline__ void ffma2(uint64_t& acc, uint64_t a, uint64_t b) {
    asm("fma.rn.f32x2 %0, %1, %2, %0;" : "+l"(acc) : "l"(a), "l"(b));
}
__device__ __forceinline__ uint64_t rep2(float x) {
    uint64_t r;
    asm("mov.b64 %0, {%1, %1};" : "=l"(r) : "f"(x));
    return r;
}
__device__ __forceinline__ uint64_t pack2(float lo, float hi) {
    uint64_t r;
    asm("mov.b64 %0, {%1, %2};" : "=l"(r) : "f"(lo), "f"(hi));
    return r;
}
__device__ __forceinline__ void unpack2(uint64_t v, float& lo, float& hi) {
    asm("mov.b64 {%0, %1}, %2;" : "=f"(lo), "=f"(hi) : "l"(v));
}

// Core FFMA2 block for one k4 step over 10 m-rows
__device__ __forceinline__ void fma_block10(
    uint64_t acc[10][2], const float4& w0, const float4& w1,
    const float4& w2, const float4& w3,
    const float* __restrict__ X, int xs, int m0, int k)
{
    const uint64_t wa0 = pack2(w0.x, w0.y), wb0 = pack2(w0.z, w0.w);
    const uint64_t wa1 = pack2(w1.x, w1.y), wb1 = pack2(w1.z, w1.w);
    const uint64_t wa2 = pack2(w2.x, w2.y), wb2 = pack2(w2.z, w2.w);
    const uint64_t wa3 = pack2(w3.x, w3.y), wb3 = pack2(w3.z, w3.w);
#pragma unroll
    for (int i = 0; i < 10; i++) {
        const float4 xv = *(const float4*)(X + (m0 + i) * xs + k);
        const uint64_t x0 = rep2(xv.x);
        ffma2(acc[i][0], x0, wa0);
        ffma2(acc[i][1], x0, wb0);
        const uint64_t x1 = rep2(xv.y);
        ffma2(acc[i][0], x1, wa1);
        ffma2(acc[i][1], x1, wb1);
        const uint64_t x2 = rep2(xv.z);
        ffma2(acc[i][0], x2, wa2);
        ffma2(acc[i][1], x2, wb2);
        const uint64_t x3 = rep2(xv.w);
        ffma2(acc[i][0], x3, wa3);
        ffma2(acc[i][1], x3, wb3);
    }
}

// ---- full GEMM: OUT = act(X @ W + bias), 250 threads, 10m x 4n ----
// Warp-cooperative mapping: rg = t%5 (adjacent lanes share W lines -> L1 broadcast)
template<bool RELU>
__device__ __forceinline__ void gemm_full(
    const float* __restrict__ X, int xs,
    const float* __restrict__ W,
    const float* __restrict__ bias,
    float* __restrict__ OUT, int t)
{
    if (t < 250) {
        const int rg = t % 5, cg = t / 5;
        const int n0 = cg * 4, m0 = rg * 10;
        uint64_t acc[10][2];
#pragma unroll
        for (int i = 0; i < 10; i++) { acc[i][0] = 0ull; acc[i][1] = 0ull; }

        const float* Wp = W + n0;
#pragma unroll 2
        for (int k = 0; k < TD; k += 4) {
            const float4 w0 = __ldg((const float4*)(Wp + (k + 0) * TD));
            const float4 w1 = __ldg((const float4*)(Wp + (k + 1) * TD));
            const float4 w2 = __ldg((const float4*)(Wp + (k + 2) * TD));
            const float4 w3 = __ldg((const float4*)(Wp + (k + 3) * TD));
            fma_block10(acc, w0, w1, w2, w3, X, xs, m0, k);
        }

        const float4 bvv = __ldg((const float4*)(bias + n0));
#pragma unroll
        for (int i = 0; i < 10; i++) {
            float a0, a1, a2, a3;
            unpack2(acc[i][0], a0, a1);
            unpack2(acc[i][1], a2, a3);
            a0 += bvv.x; a1 += bvv.y; a2 += bvv.z; a3 += bvv.w;
            if (RELU) {
                a0 = fmaxf(a0, 0.0f); a1 = fmaxf(a1, 0.0f);
                a2 = fmaxf(a2, 0.0f); a3 = fmaxf(a3, 0.0f);
            }
            float* o = OUT + (m0 + i) * WS + n0;
            o[0] = a0; o[1] = a1; o[2] = a2; o[3] = a3;
        }
    }
}

// ---- partial GEMM: OUT = X[:, k0:k0+100] @ W[k0:k0+100, :] (raw, no bias) ----
__device__ __forceinline__ void gemm_part(
    const float* __restrict__ X, int xs,
    const float* __restrict__ W,
    float* __restrict__ OUT, int t, int k0)
{
    if (t < 250) {
        const int rg = t % 5, cg = t / 5;
        const int n0 = cg * 4, m0 = rg * 10;
        uint64_t acc[10][2];
#pragma unroll
        for (int i = 0; i < 10; i++) { acc[i][0] = 0ull; acc[i][1] = 0ull; }

        const float* Wp = W + n0;
#pragma unroll 2
        for (int k = k0; k < k0 + TD / 2; k += 4) {
            const float4 w0 = __ldg((const float4*)(Wp + (k + 0) * TD));
            const float4 w1 = __ldg((const float4*)(Wp + (k + 1) * TD));
            const float4 w2 = __ldg((const float4*)(Wp + (k + 2) * TD));
            const float4 w3 = __ldg((const float4*)(Wp + (k + 3) * TD));
            fma_block10(acc, w0, w1, w2, w3, X, xs, m0, k);
        }

#pragma unroll
        for (int i = 0; i < 10; i++) {
            float a0, a1, a2, a3;
            unpack2(acc[i][0], a0, a1);
            unpack2(acc[i][1], a2, a3);
            float* o = OUT + (m0 + i) * WS + n0;
            o[0] = a0; o[1] = a1; o[2] = a2; o[3] = a3;
        }
    }
}

__global__ void __launch_bounds__(NTHREADS, 1) encoder_kernel(
    const int* __restrict__ tokens, const float* __restrict__ emb,
    const float* __restrict__ Wq, const float* __restrict__ bq,
    const float* __restrict__ Wk, const float* __restrict__ bk,
    const float* __restrict__ Wv, const float* __restrict__ bv,
    const float* __restrict__ W1, const float* __restrict__ b1,
    const float* __restrict__ W2, const float* __restrict__ b2,
    const float* __restrict__ lng, const float* __restrict__ lnb,
    float* __restrict__ out)
{
    extern __shared__ float sm[];
    float* sx   = sm;                     // 50*200
    float* bufA = sx + TL * TD;           // 50*204
    float* bufB = bufA + TL * WS;         // 50*204
    float* bufV = bufB + TL * WS;         // 50*204
    float* sS   = bufV + TL * WS;         // 50*52
    float* km   = sS + TL * SSTRIDE;      // 50  (1.0 if key row masked)

    const int tid = threadIdx.x;
    const int b = blockIdx.x;
    const int warp = tid >> 5, lane = tid & 31;

    // Embedding gather: sx = emb[tokens[b]]
    {
        const int* tok = tokens + b * TL;
        for (int idx = tid; idx < TL * TD / 4; idx += NTHREADS) {
            const int m = idx / (TD / 4);
            const int c = idx - m * (TD / 4);
            const int t = __ldg(tok + m);
            ((float4*)sx)[idx] = __ldg((const float4*)emb + (size_t)t * (TD / 4) + c);
        }
    }

    for (int blk = 0; blk < NBLK; blk++) {
        const float* wq = Wq + blk * TD * TD;
        const float* wk = Wk + blk * TD * TD;
        const float* wv = Wv + blk * TD * TD;
        const float* w1 = W1 + blk * TD * TD;
        const float* w2 = W2 + blk * TD * TD;
        const float* bq_ = bq + blk * TD;
        const float* bk_ = bk + blk * TD;
        const float* bv_ = bv + blk * TD;
        const float* b1_ = b1 + blk * TD;
        const float* b2_ = b2 + blk * TD;
        const float* g_  = lng + blk * TD;
        const float* be_ = lnb + blk * TD;

        __syncthreads();   // sx ready (gather or previous LN)

        // Row masks: km[r] = 1 if sum(x[r,:]) == 0
        for (int r = warp; r < TL; r += NTHREADS / 32) {
            float s = 0.0f;
            for (int c = lane; c < TD; c += 32) s += sx[r * TD + c];
            s = wsum(s);
            if (lane == 0) km[r] = (s == 0.0f) ? 1.0f : 0.0f;
        }

        // Q (group 0) || K (group 1)
        if (tid < 256) gemm_full<true>(sx, TD, wq, bq_, bufA, tid);
        else           gemm_full<true>(sx, TD, wk, bk_, bufB, tid - 256);
        __syncthreads();

        // scores (group 0, 250 thr) || V (group 1)
        if (tid < 256) {
            if (tid < 250) {
                const int kk0 = (tid % 5) * 10;   // adjacent lanes share K rows
                const int q = tid / 5;
                uint64_t acc[10];
#pragma unroll
                for (int j = 0; j < 10; j++) acc[j] = 0ull;
#pragma unroll 2
                for (int d = 0; d < TD; d += 4) {
                    const float4 qa = *(const float4*)(bufA + q * WS + d);
                    const uint64_t q01 = pack2(qa.x, qa.y);
                    const uint64_t q23 = pack2(qa.z, qa.w);
#pragma unroll
                    for (int j = 0; j < 10; j++) {
                        const float4 kv = *(const float4*)(bufB + (kk0 + j) * WS + d);
                        ffma2(acc[j], q01, pack2(kv.x, kv.y));
                        ffma2(acc[j], q23, pack2(kv.z, kv.w));
                    }
                }
                const float scale = 0.07071067811865475f;  // 1/sqrt(200)
#pragma unroll
                for (int j = 0; j < 10; j++) {
                    float lo, hi;
                    unpack2(acc[j], lo, hi);
                    sS[q * SSTRIDE + kk0 + j] =
                        (km[kk0 + j] != 0.0f) ? NEGV : (lo + hi) * scale;
                }
            }
        } else {
            gemm_full<true>(sx, TD, wv, bv_, bufV, tid - 256);
        }
        __syncthreads();

        // Softmax over rows of sS, then * query mask
        for (int q = warp; q < TL; q += NTHREADS / 32) {
            const float a  = sS[q * SSTRIDE + lane];
            const float bb = (lane < TL - 32) ? sS[q * SSTRIDE + 32 + lane] : -3.4e38f;
            const float mx = wmax(fmaxf(a, bb));
            const float ea = expf(a - mx);
            const float eb = (lane < TL - 32) ? expf(bb - mx) : 0.0f;
            const float ssum = wsum(ea + eb);
            const float fac = (1.0f - km[q]) / ssum;
            sS[q * SSTRIDE + lane] = ea * fac;
            if (lane < TL - 32) sS[q * SSTRIDE + 32 + lane] = eb * fac;
        }
        __syncthreads();

        // x += attn @ V   (500 threads, n-packed FFMA2, lanes share V lines)
        if (tid < 500) {
            const int rg = tid % 10, cg = tid / 10;
            const int n0 = cg * 4, m0 = rg * 5;
            uint64_t acc[5][2];
#pragma unroll
            for (int i = 0; i < 5; i++) { acc[i][0] = 0ull; acc[i][1] = 0ull; }
#pragma unroll 2
            for (int kk = 0; kk < TL; kk++) {
                const float4 v = *(const float4*)(bufV + kk * WS + n0);
                const uint64_t v01 = pack2(v.x, v.y);
                const uint64_t v23 = pack2(v.z, v.w);
#pragma unroll
                for (int i = 0; i < 5; i++) {
                    const uint64_t a = rep2(sS[(m0 + i) * SSTRIDE + kk]);
                    ffma2(acc[i][0], a, v01);
                    ffma2(acc[i][1], a, v23);
                }
            }
#pragma unroll
            for (int i = 0; i < 5; i++) {
                float a0, a1, a2, a3;
                unpack2(acc[i][0], a0, a1);
                unpack2(acc[i][1], a2, a3);
                float* o = sx + (m0 + i) * TD + n0;
                o[0] += a0; o[1] += a1; o[2] += a2; o[3] += a3;
            }
        }
        __syncthreads();

        // FFN1 k-split: group0 k=[0,100) -> bufA, group1 k=[100,200) -> bufB
        if (tid < 256) gemm_part(sx, TD, w1, bufA, tid, 0);
        else           gemm_part(sx, TD, w1, bufB, tid - 256, TD / 2);
        __syncthreads();

        // merge: bufA = relu(bufA + bufB + b1)
        for (int idx = tid; idx < TL * TD / 4; idx += NTHREADS) {
            const int r = idx / (TD / 4), c4 = idx % (TD / 4);
            float4 a = ((const float4*)(bufA + r * WS))[c4];
            float4 p = ((const float4*)(bufB + r * WS))[c4];
            const float4 bb = __ldg((const float4*)b1_ + c4);
            a.x = fmaxf(a.x + p.x + bb.x, 0.0f);
            a.y = fmaxf(a.y + p.y + bb.y, 0.0f);
            a.z = fmaxf(a.z + p.z + bb.z, 0.0f);
            a.w = fmaxf(a.w + p.w + bb.w, 0.0f);
            ((float4*)(bufA + r * WS))[c4] = a;
        }
        __syncthreads();

        // FFN2 k-split: group0 k=[0,100) -> bufB, group1 k=[100,200) -> bufV
        if (tid < 256) gemm_part(bufA, WS, w2, bufB, tid, 0);
        else           gemm_part(bufA, WS, w2, bufV, tid - 256, TD / 2);
        __syncthreads();

        // LayerNorm( bufB + bufV + b2 ) * g + be, residual into sx
        for (int r = warp; r < TL; r += NTHREADS / 32) {
            float hbuf[7];
            int nc = 0;
            float s = 0.0f;
            for (int c = lane; c < TD; c += 32) {
                const float h = bufB[r * WS + c] + bufV[r * WS + c] + __ldg(b2_ + c);
                hbuf[nc++] = h;
                s += h;
            }
            s = wsum(s);
            const float mu = s * (1.0f / TD);
            float v = 0.0f;
            for (int i = 0; i < nc; i++) {
                const float dd = hbuf[i] - mu;
                v = fmaf(dd, dd, v);
            }
            v = wsum(v);
            const float inv = rsqrtf(v * (1.0f / TD) + LNEPS);
            nc = 0;
            for (int c = lane; c < TD; c += 32) {
                const float y = (hbuf[nc++] - mu) * inv * __ldg(g_ + c) + __ldg(be_ + c);
                sx[r * TD + c] += y;
            }
        }
    }
    __syncthreads();

    // Write out
    {
        float4* o = (float4*)(out + (size_t)b * TL * TD);
        for (int idx = tid; idx < TL * TD / 4; idx += NTHREADS)
            o[idx] = ((const float4*)sx)[idx];
    }
}

extern "C" void kernel_launch(void* const* d_in, const int* in_sizes, int n_in,
                              void* d_out, int out_size) {
    const int*   tokens = (const int*)d_in[0];
    const float* emb = (const float*)d_in[1];
    const float* Wq  = (const float*)d_in[2];
    const float* bq  = (const float*)d_in[3];
    const float* Wk  = (const float*)d_in[4];
    const float* bk  = (const float*)d_in[5];
    const float* Wv  = (const float*)d_in[6];
    const float* bv  = (const float*)d_in[7];
    const float* W1  = (const float*)d_in[8];
    const float* b1  = (const float*)d_in[9];
    const float* W2  = (const float*)d_in[10];
    const float* b2  = (const float*)d_in[11];
    const float* lng = (const float*)d_in[12];
    const float* lnb = (const float*)d_in[13];
    float* out = (float*)d_out;

    const int B = in_sizes[0] / TL;
    const size_t smem = (size_t)(TL * TD + 3 * TL * WS + TL * SSTRIDE + TL) * sizeof(float);

    cudaFuncSetAttribute(encoder_kernel,
                         cudaFuncAttributeMaxDynamicSharedMemorySize, (int)smem);
    encoder_kernel<<<B, NTHREADS, smem>>>(tokens, emb, Wq, bq, Wk, bk, Wv, bv,
                                          W1, b1, W2, b2, lng, lnb, out);
}

// round 7
// speedup vs baseline: 1.7111x; 1.5704x over previous
#include <cuda_runtime.h>
#include <math.h>
#include <stdint.h>

#define TL 50
#define TD 200
#define NBLK 3
#define NTHREADS 512
#define WS 204           // padded row stride for work buffers
#define SSTRIDE 52       // padded row stride for scores
#define NEGV (-4294967296.0f)   // float32(-2^32+1)
#define LNEPS 1e-8f

#define STG_ROWS 8                   // rows per ring stage
#define STG_FLOATS (STG_ROWS * TD)   // 1600 floats per stage
#define RING_DEPTH 3
#define RING_FLOATS (RING_DEPTH * STG_FLOATS)  // 4800 floats per ring

__device__ __forceinline__ float wsum(float v) {
#pragma unroll
    for (int o = 16; o > 0; o >>= 1) v += __shfl_xor_sync(0xffffffffu, v, o);
    return v;
}
__device__ __forceinline__ float wmax(float v) {
#pragma unroll
    for (int o = 16; o > 0; o >>= 1) v = fmaxf(v, __shfl_xor_sync(0xffffffffu, v, o));
    return v;
}

// ---- packed fp32x2 helpers (Blackwell FFMA2) ----
__device__ __forceinline__ void ffma2(uint64_t& acc, uint64_t a, uint64_t b) {
    asm("fma.rn.f32x2 %0, %1, %2, %0;" : "+l"(acc) : "l"(a), "l"(b));
}
__device__ __forceinline__ uint64_t rep2(float x) {
    uint64_t r;
    asm("mov.b64 %0, {%1, %1};" : "=l"(r) : "f"(x));
    return r;
}
__device__ __forceinline__ uint64_t pack2(float lo, float hi) {
    uint64_t r;
    asm("mov.b64 %0, {%1, %2};" : "=l"(r) : "f"(lo), "f"(hi));
    return r;
}
__device__ __forceinline__ void unpack2(uint64_t v, float& lo, float& hi) {
    asm("mov.b64 {%0, %1}, %2;" : "=f"(lo), "=f"(hi) : "l"(v));
}

__device__ __forceinline__ void group_bar(int id) {
    asm volatile("bar.sync %0, %1;" :: "r"(id), "r"(256) : "memory");
}

// Producer: stage = 8 rows x 200 floats = 400 x 16B chunks, 256 threads
__device__ __forceinline__ void ring_produce(
    float* ring, int slot, const float* __restrict__ Wstage, int t)
{
    uint32_t base = (uint32_t)__cvta_generic_to_shared(ring + slot * STG_FLOATS);
#pragma unroll
    for (int idx = t; idx < 400; idx += 256) {
        const int r = idx / 50, c = idx % 50;
        const float* g = Wstage + r * TD + c * 4;
        const uint32_t d = base + (uint32_t)(r * TD + c * 4) * 4u;
        asm volatile("cp.async.ca.shared.global [%0], [%1], 16;" :: "r"(d), "l"(g));
    }
    asm volatile("cp.async.commit_group;" ::: "memory");
}

// Core FFMA2 block for one k4 step over 10 m-rows
__device__ __forceinline__ void fma_block10(
    uint64_t acc[10][2], const float4& w0, const float4& w1,
    const float4& w2, const float4& w3,
    const float* __restrict__ X, int xs, int m0, int k)
{
    const uint64_t wa0 = pack2(w0.x, w0.y), wb0 = pack2(w0.z, w0.w);
    const uint64_t wa1 = pack2(w1.x, w1.y), wb1 = pack2(w1.z, w1.w);
    const uint64_t wa2 = pack2(w2.x, w2.y), wb2 = pack2(w2.z, w2.w);
    const uint64_t wa3 = pack2(w3.x, w3.y), wb3 = pack2(w3.z, w3.w);
#pragma unroll
    for (int i = 0; i < 10; i++) {
        const float4 xv = *(const float4*)(X + (m0 + i) * xs + k);
        const uint64_t x0 = rep2(xv.x);
        ffma2(acc[i][0], x0, wa0);
        ffma2(acc[i][1], x0, wb0);
        const uint64_t x1 = rep2(xv.y);
        ffma2(acc[i][0], x1, wa1);
        ffma2(acc[i][1], x1, wb1);
        const uint64_t x2 = rep2(xv.z);
        ffma2(acc[i][0], x2, wa2);
        ffma2(acc[i][1], x2, wb2);
        const uint64_t x3 = rep2(xv.w);
        ffma2(acc[i][0], x3, wa3);
        ffma2(acc[i][1], x3, wb3);
    }
}

// ---- ring-staged GEMM: OUT = act(X[:,krow0:krow0+8*S] @ W[krow0:...,:] (+bias))
// 256 threads per group run barriers/producer; 250 consume (10m x 4n tiles,
// R4 mapping: rg=t/50 -> whole warp shares X row; cg=t%50 -> coalesced W LDS).
template<bool RELU, bool BIAS>
__device__ __forceinline__ void gemm_ring(
    const float* __restrict__ X, int xs,
    const float* __restrict__ W,
    const float* __restrict__ bias,
    float* __restrict__ OUT,
    int t, float* ring, int bar_id, int krow0, int nstages)
{
    // prologue: stages 0 and 1 in flight
    ring_produce(ring, 0, W + krow0 * TD, t);
    ring_produce(ring, 1, W + (krow0 + STG_ROWS) * TD, t);

    const int cg = t % 50, rg = t / 50;
    const int n0 = cg * 4, m0 = rg * 10;
    uint64_t acc[10][2];
#pragma unroll
    for (int i = 0; i < 10; i++) { acc[i][0] = 0ull; acc[i][1] = 0ull; }

#pragma unroll 1
    for (int s = 0; s < nstages; s++) {
        if (s + 1 < nstages)
            asm volatile("cp.async.wait_group 1;" ::: "memory");
        else
            asm volatile("cp.async.wait_group 0;" ::: "memory");
        group_bar(bar_id);
        if (s + 2 < nstages)
            ring_produce(ring, (s + 2) % RING_DEPTH,
                         W + (krow0 + (s + 2) * STG_ROWS) * TD, t);
        if (t < 250) {
            const float* wr = ring + (s % RING_DEPTH) * STG_FLOATS + n0;
            const int kg = krow0 + s * STG_ROWS;
#pragma unroll
            for (int h = 0; h < 2; h++) {
                const float4 w0 = *(const float4*)(wr + (h * 4 + 0) * TD);
                const float4 w1 = *(const float4*)(wr + (h * 4 + 1) * TD);
                const float4 w2 = *(const float4*)(wr + (h * 4 + 2) * TD);
                const float4 w3 = *(const float4*)(wr + (h * 4 + 3) * TD);
                fma_block10(acc, w0, w1, w2, w3, X, xs, m0, kg + h * 4);
            }
        }
    }

    if (t < 250) {
        float bx = 0.f, by = 0.f, bz = 0.f, bw = 0.f;
        if (BIAS) {
            const float4 bvv = __ldg((const float4*)(bias + n0));
            bx = bvv.x; by = bvv.y; bz = bvv.z; bw = bvv.w;
        }
#pragma unroll
        for (int i = 0; i < 10; i++) {
            float a0, a1, a2, a3;
            unpack2(acc[i][0], a0, a1);
            unpack2(acc[i][1], a2, a3);
            a0 += bx; a1 += by; a2 += bz; a3 += bw;
            if (RELU) {
                a0 = fmaxf(a0, 0.0f); a1 = fmaxf(a1, 0.0f);
                a2 = fmaxf(a2, 0.0f); a3 = fmaxf(a3, 0.0f);
            }
            float* o = OUT + (m0 + i) * WS + n0;
            o[0] = a0; o[1] = a1; o[2] = a2; o[3] = a3;
        }
    }
}

__global__ void __launch_bounds__(NTHREADS, 1) encoder_kernel(
    const int* __restrict__ tokens, const float* __restrict__ emb,
    const float* __restrict__ Wq, const float* __restrict__ bq,
    const float* __restrict__ Wk, const float* __restrict__ bk,
    const float* __restrict__ Wv, const float* __restrict__ bv,
    const float* __restrict__ W1, const float* __restrict__ b1,
    const float* __restrict__ W2, const float* __restrict__ b2,
    const float* __restrict__ lng, const float* __restrict__ lnb,
    float* __restrict__ out)
{
    extern __shared__ float sm[];
    float* sx    = sm;                     // 50*200
    float* bufA  = sx + TL * TD;           // 50*204
    float* bufB  = bufA + TL * WS;         // 50*204
    float* bufV  = bufB + TL * WS;         // 50*204
    float* sS    = bufV + TL * WS;         // 50*52
    float* km    = sS + TL * SSTRIDE;      // 64 (padded; 1.0 if key row masked)
    float* ring0 = km + 64;                // 4800
    float* ring1 = ring0 + RING_FLOATS;    // 4800

    const int tid = threadIdx.x;
    const int b = blockIdx.x;
    const int warp = tid >> 5, lane = tid & 31;

    // Embedding gather: sx = emb[tokens[b]]
    {
        const int* tok = tokens + b * TL;
        for (int idx = tid; idx < TL * TD / 4; idx += NTHREADS) {
            const int m = idx / (TD / 4);
            const int c = idx - m * (TD / 4);
            const int t = __ldg(tok + m);
            ((float4*)sx)[idx] = __ldg((const float4*)emb + (size_t)t * (TD / 4) + c);
        }
    }

    for (int blk = 0; blk < NBLK; blk++) {
        const float* wq = Wq + blk * TD * TD;
        const float* wk = Wk + blk * TD * TD;
        const float* wv = Wv + blk * TD * TD;
        const float* w1 = W1 + blk * TD * TD;
        const float* w2 = W2 + blk * TD * TD;
        const float* bq_ = bq + blk * TD;
        const float* bk_ = bk + blk * TD;
        const float* bv_ = bv + blk * TD;
        const float* b1_ = b1 + blk * TD;
        const float* b2_ = b2 + blk * TD;
        const float* g_  = lng + blk * TD;
        const float* be_ = lnb + blk * TD;

        __syncthreads();   // sx ready (gather or previous LN)

        // Row masks: km[r] = 1 if sum(x[r,:]) == 0
        for (int r = warp; r < TL; r += NTHREADS / 32) {
            float s = 0.0f;
            for (int c = lane; c < TD; c += 32) s += sx[r * TD + c];
            s = wsum(s);
            if (lane == 0) km[r] = (s == 0.0f) ? 1.0f : 0.0f;
        }

        // Q (group 0, ring0) || K (group 1, ring1)
        if (tid < 256)
            gemm_ring<true, true>(sx, TD, wq, bq_, bufA, tid, ring0, 1, 0, 25);
        else
            gemm_ring<true, true>(sx, TD, wk, bk_, bufB, tid - 256, ring1, 2, 0, 25);
        __syncthreads();

        // scores (group 0, barrier-free) || V (group 1, ring1)
        if (tid < 256) {
            if (tid < 250) {
                const int q = tid / 5;
                const int kk0 = (tid % 5) * 10;
                uint64_t acc[10];
#pragma unroll
                for (int j = 0; j < 10; j++) acc[j] = 0ull;
#pragma unroll 2
                for (int d = 0; d < TD; d += 4) {
                    const float4 qa = *(const float4*)(bufA + q * WS + d);
                    const uint64_t q01 = pack2(qa.x, qa.y);
                    const uint64_t q23 = pack2(qa.z, qa.w);
#pragma unroll
                    for (int j = 0; j < 10; j++) {
                        const float4 kv = *(const float4*)(bufB + (kk0 + j) * WS + d);
                        ffma2(acc[j], q01, pack2(kv.x, kv.y));
                        ffma2(acc[j], q23, pack2(kv.z, kv.w));
                    }
                }
                const float scale = 0.07071067811865475f;  // 1/sqrt(200)
#pragma unroll
                for (int j = 0; j < 10; j++) {
                    float lo, hi;
                    unpack2(acc[j], lo, hi);
                    sS[q * SSTRIDE + kk0 + j] =
                        (km[kk0 + j] != 0.0f) ? NEGV : (lo + hi) * scale;
                }
            }
        } else {
            gemm_ring<true, true>(sx, TD, wv, bv_, bufV, tid - 256, ring1, 2, 0, 25);
        }
        __syncthreads();

        // Softmax over rows of sS, then * query mask
        for (int q = warp; q < TL; q += NTHREADS / 32) {
            const float a  = sS[q * SSTRIDE + lane];
            const float bb = (lane < TL - 32) ? sS[q * SSTRIDE + 32 + lane] : -3.4e38f;
            const float mx = wmax(fmaxf(a, bb));
            const float ea = expf(a - mx);
            const float eb = (lane < TL - 32) ? expf(bb - mx) : 0.0f;
            const float ssum = wsum(ea + eb);
            const float fac = (1.0f - km[q]) / ssum;
            sS[q * SSTRIDE + lane] = ea * fac;
            if (lane < TL - 32) sS[q * SSTRIDE + 32 + lane] = eb * fac;
        }
        __syncthreads();

        // x += attn @ V   (500 threads, n-packed FFMA2)
        if (tid < 500) {
            const int cg = tid % 50, rg = tid / 50;
            const int n0 = cg * 4, m0 = rg * 5;
            uint64_t acc[5][2];
#pragma unroll
            for (int i = 0; i < 5; i++) { acc[i][0] = 0ull; acc[i][1] = 0ull; }
#pragma unroll 2
            for (int kk = 0; kk < TL; kk++) {
                const float4 v = *(const float4*)(bufV + kk * WS + n0);
                const uint64_t v01 = pack2(v.x, v.y);
                const uint64_t v23 = pack2(v.z, v.w);
#pragma unroll
                for (int i = 0; i < 5; i++) {
                    const uint64_t a = rep2(sS[(m0 + i) * SSTRIDE + kk]);
                    ffma2(acc[i][0], a, v01);
                    ffma2(acc[i][1], a, v23);
                }
            }
#pragma unroll
            for (int i = 0; i < 5; i++) {
                float a0, a1, a2, a3;
                unpack2(acc[i][0], a0, a1);
                unpack2(acc[i][1], a2, a3);
                float* o = sx + (m0 + i) * TD + n0;
                o[0] += a0; o[1] += a1; o[2] += a2; o[3] += a3;
            }
        }
        __syncthreads();

        // FFN1 k-split: g0 k=[0,104) -> bufA (13 stages), g1 k=[104,200) -> bufB (12)
        if (tid < 256)
            gemm_ring<false, false>(sx, TD, w1, b1_, bufA, tid, ring0, 1, 0, 13);
        else
            gemm_ring<false, false>(sx, TD, w1, b1_, bufB, tid - 256, ring1, 2, 104, 12);
        __syncthreads();

        // merge: bufA = relu(bufA + bufB + b1)
        for (int idx = tid; idx < TL * TD / 4; idx += NTHREADS) {
            const int r = idx / (TD / 4), c4 = idx % (TD / 4);
            float4 a = ((const float4*)(bufA + r * WS))[c4];
            float4 p = ((const float4*)(bufB + r * WS))[c4];
            const float4 bb = __ldg((const float4*)b1_ + c4);
            a.x = fmaxf(a.x + p.x + bb.x, 0.0f);
            a.y = fmaxf(a.y + p.y + bb.y, 0.0f);
            a.z = fmaxf(a.z + p.z + bb.z, 0.0f);
            a.w = fmaxf(a.w + p.w + bb.w, 0.0f);
            ((float4*)(bufA + r * WS))[c4] = a;
        }
        __syncthreads();

        // FFN2 k-split: g0 k=[0,104) -> bufB, g1 k=[104,200) -> bufV
        if (tid < 256)
            gemm_ring<false, false>(bufA, WS, w2, b2_, bufB, tid, ring0, 1, 0, 13);
        else
            gemm_ring<false, false>(bufA, WS, w2, b2_, bufV, tid - 256, ring1, 2, 104, 12);
        __syncthreads();

        // LayerNorm( bufB + bufV + b2 ) * g + be, residual into sx
        for (int r = warp; r < TL; r += NTHREADS / 32) {
            float hbuf[7];
            int nc = 0;
            float s = 0.0f;
            for (int c = lane; c < TD; c += 32) {
                const float h = bufB[r * WS + c] + bufV[r * WS + c] + __ldg(b2_ + c);
                hbuf[nc++] = h;
                s += h;
            }
            s = wsum(s);
            const float mu = s * (1.0f / TD);
            float v = 0.0f;
            for (int i = 0; i < nc; i++) {
                const float dd = hbuf[i] - mu;
                v = fmaf(dd, dd, v);
            }
            v = wsum(v);
            const float inv = rsqrtf(v * (1.0f / TD) + LNEPS);
            nc = 0;
            for (int c = lane; c < TD; c += 32) {
                const float y = (hbuf[nc++] - mu) * inv * __ldg(g_ + c) + __ldg(be_ + c);
                sx[r * TD + c] += y;
            }
        }
    }
    __syncthreads();

    // Write out
    {
        float4* o = (float4*)(out + (size_t)b * TL * TD);
        for (int idx = tid; idx < TL * TD / 4; idx += NTHREADS)
            o[idx] = ((const float4*)sx)[idx];
    }
}

extern "C" void kernel_launch(void* const* d_in, const int* in_sizes, int n_in,
                              void* d_out, int out_size) {
    const int*   tokens = (const int*)d_in[0];
    const float* emb = (const float*)d_in[1];
    const float* Wq  = (const float*)d_in[2];
    const float* bq  = (const float*)d_in[3];
    const float* Wk  = (const float*)d_in[4];
    const float* bk  = (const float*)d_in[5];
    const float* Wv  = (const float*)d_in[6];
    const float* bv  = (const float*)d_in[7];
    const float* W1  = (const float*)d_in[8];
    const float* b1  = (const float*)d_in[9];
    const float* W2  = (const float*)d_in[10];
    const float* b2  = (const float*)d_in[11];
    const float* lng = (const float*)d_in[12];
    const float* lnb = (const float*)d_in[13];
    float* out = (float*)d_out;

    const int B = in_sizes[0] / TL;
    const size_t smem =
        (size_t)(TL * TD + 3 * TL * WS + TL * SSTRIDE + 64 + 2 * RING_FLOATS)
        * sizeof(float);

    cudaFuncSetAttribute(encoder_kernel,
                         cudaFuncAttributeMaxDynamicSharedMemorySize, (int)smem);
    encoder_kernel<<<B, NTHREADS, smem>>>(tokens, emb, Wq, bq, Wk, bk, Wv, bv,
                                          W1, b1, W2, b2, lng, lnb, out);
}

// round 9
// speedup vs baseline: 2.2863x; 1.3362x over previous
#include <cuda_runtime.h>
#include <cuda_bf16.h>
#include <math.h>
#include <stdint.h>

#define TL 50
#define TD 200
#define KPAD 208          // padded K in global bf16 weights
#define KSPAD 216         // A row stride in SMEM (bf16 elems) -> 432B, ldsm conflict-free
#define NBLK 3
#define NTHREADS 512
#define WS 204
#define SSTRIDE 52
#define NEGV (-4294967296.0f)
#define LNEPS 1e-8f
#define KSTEPS 13         // 13 x k16 = 208

// SMEM byte offsets
#define SM_AHI 0
#define SM_ALO 27648                    // 64*216*2
#define SM_SX  55296
#define SM_A   (SM_SX + 40800)          // 96096
#define SM_B   (SM_A + 40800)           // 136896
#define SM_V   (SM_B + 40800)           // 177696
#define SM_SS  (SM_V + 40800)           // 218496
#define SM_KM  (SM_SS + 10400)          // 228896
#define SM_TOTAL (SM_KM + 256)          // 229152

// Pre-converted transposed weights: [mat(15)][n(200)][KPAD] bf16 (== col-major B)
__device__ __nv_bfloat16 g_whi[15 * TD * KPAD];
__device__ __nv_bfloat16 g_wlo[15 * TD * KPAD];

// ---------------- SIMT helpers ----------------
__device__ __forceinline__ float wsum(float v) {
#pragma unroll
    for (int o = 16; o > 0; o >>= 1) v += __shfl_xor_sync(0xffffffffu, v, o);
    return v;
}
__device__ __forceinline__ float wmax(float v) {
#pragma unroll
    for (int o = 16; o > 0; o >>= 1) v = fmaxf(v, __shfl_xor_sync(0xffffffffu, v, o));
    return v;
}
__device__ __forceinline__ void ffma2(uint64_t& acc, uint64_t a, uint64_t b) {
    asm("fma.rn.f32x2 %0, %1, %2, %0;" : "+l"(acc) : "l"(a), "l"(b));
}
__device__ __forceinline__ uint64_t rep2(float x) {
    uint64_t r; asm("mov.b64 %0, {%1, %1};" : "=l"(r) : "f"(x)); return r;
}
__device__ __forceinline__ uint64_t pack2(float lo, float hi) {
    uint64_t r; asm("mov.b64 %0, {%1, %2};" : "=l"(r) : "f"(lo), "f"(hi)); return r;
}
__device__ __forceinline__ void unpack2(uint64_t v, float& lo, float& hi) {
    asm("mov.b64 {%0, %1}, %2;" : "=f"(lo), "=f"(hi) : "l"(v));
}

// ---------------- MMA helpers ----------------
__device__ __forceinline__ void ldsm_x4(uint32_t r[4], uint32_t addr) {
    asm volatile("ldmatrix.sync.aligned.m8n8.x4.shared.b16 {%0,%1,%2,%3}, [%4];"
                 : "=r"(r[0]), "=r"(r[1]), "=r"(r[2]), "=r"(r[3]) : "r"(addr));
}
__device__ __forceinline__ void mma16816(float c[4], const uint32_t a[4],
                                         uint32_t b0, uint32_t b1) {
    asm volatile(
        "mma.sync.aligned.m16n8k16.row.col.f32.bf16.bf16.f32 "
        "{%0,%1,%2,%3}, {%4,%5,%6,%7}, {%8,%9}, {%0,%1,%2,%3};"
        : "+f"(c[0]), "+f"(c[1]), "+f"(c[2]), "+f"(c[3])
        : "r"(a[0]), "r"(a[1]), "r"(a[2]), "r"(a[3]), "r"(b0), "r"(b1));
}
__device__ __forceinline__ uint32_t cvt_bf16x2(float hi, float lo) {
    uint32_t h;
    asm("cvt.rn.satfinite.bf16x2.f32 %0, %1, %2;" : "=r"(h) : "f"(hi), "f"(lo));
    return h;
}

// ---------------- prep kernel: W[k][n] f32 -> transposed bf16 hi/lo ----------------
__global__ void prep_kernel(const float* __restrict__ Wq, const float* __restrict__ Wk,
                            const float* __restrict__ Wv, const float* __restrict__ W1,
                            const float* __restrict__ W2) {
    const int mat = blockIdx.x;       // 0..14
    const int n = blockIdx.y;         // 0..199
    const int blk = mat / 5, wh = mat % 5;
    const float* W = (wh == 0 ? Wq : wh == 1 ? Wk : wh == 2 ? Wv : wh == 3 ? W1 : W2)
                     + blk * TD * TD;
    const size_t base = ((size_t)mat * TD + n) * KPAD;
    for (int k = threadIdx.x; k < KPAD; k += blockDim.x) {
        const float v = (k < TD) ? __ldg(W + k * TD + n) : 0.0f;
        const __nv_bfloat16 h = __float2bfloat16(v);
        g_whi[base + k] = h;
        g_wlo[base + k] = __float2bfloat16(v - __bfloat162float(h));
    }
}

// ---------------- convert A: f32 (stride WS) -> bf16 hi/lo SMEM [64][KSPAD] ----------------
__device__ __forceinline__ void convert_A(const float* __restrict__ src,
                                          char* smem, int tid) {
    __nv_bfloat16* hi = (__nv_bfloat16*)(smem + SM_AHI);
    __nv_bfloat16* lo = (__nv_bfloat16*)(smem + SM_ALO);
    for (int idx = tid; idx < TL * (TD / 2); idx += NTHREADS) {
        const int row = idx / (TD / 2);
        const int c2 = (idx - row * (TD / 2)) * 2;
        const float x0 = src[row * WS + c2];
        const float x1 = src[row * WS + c2 + 1];
        const uint32_t h = cvt_bf16x2(x1, x0);
        const float h0 = __uint_as_float(h << 16);
        const float h1 = __uint_as_float(h & 0xffff0000u);
        const uint32_t l = cvt_bf16x2(x1 - h1, x0 - h0);
        *(uint32_t*)(hi + row * KSPAD + c2) = h;
        *(uint32_t*)(lo + row * KSPAD + c2) = l;
    }
}

// ---------------- tensor-core GEMM: dst[50,200] = act(A @ W^T + bias) ----------------
// A: SMEM bf16 hi/lo [64][KSPAD]; W: global bf16 hi/lo [200][KPAD] (col-major B).
// 16 warps; warp w owns n8-tiles {w, w+16}. No intra-GEMM syncs.
__device__ __forceinline__ void gemm_mma(const __nv_bfloat16* __restrict__ gWhi,
                                         const __nv_bfloat16* __restrict__ gWlo,
                                         const float* __restrict__ bias,
                                         float* __restrict__ dst, bool relu,
                                         char* smem, uint32_t smem_u32, int tid) {
    const int w = tid >> 5, lane = tid & 31;
    const int gid = lane >> 2, tig = lane & 3;
    // ldmatrix lane address base (group g: rows+8*(g&1), k +8*(g>>1))
    const uint32_t abase = smem_u32 + ((uint32_t)((lane & 15) * KSPAD + (lane >> 4) * 8)) * 2u;

#pragma unroll 1
    for (int nt = w; nt < 25; nt += 16) {
        float c[4][4];
#pragma unroll
        for (int mt = 0; mt < 4; mt++)
#pragma unroll
            for (int j = 0; j < 4; j++) c[mt][j] = 0.0f;

        const __nv_bfloat16* bh = gWhi + (nt * 8 + gid) * KPAD + 2 * tig;
        const __nv_bfloat16* bl = gWlo + (nt * 8 + gid) * KPAD + 2 * tig;

        // prefetch B for ks=0
        uint32_t pbh0 = *(const uint32_t*)(bh);
        uint32_t pbh1 = *(const uint32_t*)(bh + 8);
        uint32_t pbl0 = *(const uint32_t*)(bl);
        uint32_t pbl1 = *(const uint32_t*)(bl + 8);

#pragma unroll 1
        for (int ks = 0; ks < KSTEPS; ks++) {
            const uint32_t bh0 = pbh0, bh1 = pbh1, bl0 = pbl0, bl1 = pbl1;
            if (ks + 1 < KSTEPS) {
                pbh0 = *(const uint32_t*)(bh + (ks + 1) * 16);
                pbh1 = *(const uint32_t*)(bh + (ks + 1) * 16 + 8);
                pbl0 = *(const uint32_t*)(bl + (ks + 1) * 16);
                pbl1 = *(const uint32_t*)(bl + (ks + 1) * 16 + 8);
            }
            const uint32_t koff = (uint32_t)(ks * 16 * 2);
#pragma unroll
            for (int mt = 0; mt < 4; mt++) {
                const uint32_t aoff = (uint32_t)(mt * 16 * KSPAD * 2) + koff;
                uint32_t ah[4], al[4];
                ldsm_x4(ah, abase + SM_AHI + aoff);
                ldsm_x4(al, abase + SM_ALO + aoff);
                mma16816(c[mt], ah, bh0, bh1);
                mma16816(c[mt], al, bh0, bh1);
                mma16816(c[mt], ah, bl0, bl1);
            }
        }

        // epilogue
        const int col0 = nt * 8 + 2 * tig;
        const float bx = __ldg(bias + col0);
        const float by = __ldg(bias + col0 + 1);
#pragma unroll
        for (int mt = 0; mt < 4; mt++) {
            const int r0 = mt * 16 + gid;
            if (r0 < TL) {
                float v0 = c[mt][0] + bx, v1 = c[mt][1] + by;
                if (relu) { v0 = fmaxf(v0, 0.0f); v1 = fmaxf(v1, 0.0f); }
                dst[r0 * WS + col0] = v0;
                dst[r0 * WS + col0 + 1] = v1;
            }
            const int r1 = mt * 16 + gid + 8;
            if (r1 < TL) {
                float v2 = c[mt][2] + bx, v3 = c[mt][3] + by;
                if (relu) { v2 = fmaxf(v2, 0.0f); v3 = fmaxf(v3, 0.0f); }
                dst[r1 * WS + col0] = v2;
                dst[r1 * WS + col0 + 1] = v3;
            }
        }
    }
}

// ---------------- main kernel ----------------
__global__ void __launch_bounds__(NTHREADS, 1) encoder_kernel(
    const int* __restrict__ tokens, const float* __restrict__ emb,
    const float* __restrict__ bq, const float* __restrict__ bk,
    const float* __restrict__ bv, const float* __restrict__ b1,
    const float* __restrict__ b2,
    const float* __restrict__ lng, const float* __restrict__ lnb,
    float* __restrict__ out)
{
    extern __shared__ char smem[];
    const uint32_t smem_u32 = (uint32_t)__cvta_generic_to_shared(smem);
    float* sx   = (float*)(smem + SM_SX);
    float* bufA = (float*)(smem + SM_A);
    float* bufB = (float*)(smem + SM_B);
    float* bufV = (float*)(smem + SM_V);
    float* sS   = (float*)(smem + SM_SS);
    float* km   = (float*)(smem + SM_KM);

    const int tid = threadIdx.x;
    const int b = blockIdx.x;
    const int warp = tid >> 5, lane = tid & 31;

    // zero A bf16 buffers (padding rows/cols stay zero forever)
    {
        uint32_t* az = (uint32_t*)(smem + SM_AHI);
        for (int i = tid; i < (2 * 64 * KSPAD) / 2; i += NTHREADS) az[i] = 0u;
    }
    // Embedding gather: sx = emb[tokens[b]]  (stride WS)
    {
        const int* tok = tokens + b * TL;
        for (int idx = tid; idx < TL * (TD / 4); idx += NTHREADS) {
            const int m = idx / (TD / 4);
            const int c = idx - m * (TD / 4);
            const int t = __ldg(tok + m);
            *(float4*)(sx + m * WS + c * 4) =
                __ldg((const float4*)emb + (size_t)t * (TD / 4) + c);
        }
    }
    __syncthreads();

    for (int blk = 0; blk < NBLK; blk++) {
        const int m0 = blk * 5;
        const __nv_bfloat16* whq = g_whi + (size_t)(m0 + 0) * TD * KPAD;
        const __nv_bfloat16* wlq = g_wlo + (size_t)(m0 + 0) * TD * KPAD;
        const __nv_bfloat16* whk = g_whi + (size_t)(m0 + 1) * TD * KPAD;
        const __nv_bfloat16* wlk = g_wlo + (size_t)(m0 + 1) * TD * KPAD;
        const __nv_bfloat16* whv = g_whi + (size_t)(m0 + 2) * TD * KPAD;
        const __nv_bfloat16* wlv = g_wlo + (size_t)(m0 + 2) * TD * KPAD;
        const __nv_bfloat16* wh1 = g_whi + (size_t)(m0 + 3) * TD * KPAD;
        const __nv_bfloat16* wl1 = g_wlo + (size_t)(m0 + 3) * TD * KPAD;
        const __nv_bfloat16* wh2 = g_whi + (size_t)(m0 + 4) * TD * KPAD;
        const __nv_bfloat16* wl2 = g_wlo + (size_t)(m0 + 4) * TD * KPAD;
        const float* bq_ = bq + blk * TD;
        const float* bk_ = bk + blk * TD;
        const float* bv_ = bv + blk * TD;
        const float* b1_ = b1 + blk * TD;
        const float* b2_ = b2 + blk * TD;
        const float* g_  = lng + blk * TD;
        const float* be_ = lnb + blk * TD;

        // Row masks: km[r] = 1 if sum(x[r,:]) == 0
        for (int r = warp; r < TL; r += NTHREADS / 32) {
            float s = 0.0f;
            for (int c = lane; c < TD; c += 32) s += sx[r * WS + c];
            s = wsum(s);
            if (lane == 0) km[r] = (s == 0.0f) ? 1.0f : 0.0f;
        }
        convert_A(sx, smem, tid);
        __syncthreads();

        // Q, K, V on tensor cores (no syncs between — disjoint outputs)
        gemm_mma(whq, wlq, bq_, bufA, true, smem, smem_u32, tid);
        gemm_mma(whk, wlk, bk_, bufB, true, smem, smem_u32, tid);
        gemm_mma(whv, wlv, bv_, bufV, true, smem, smem_u32, tid);
        __syncthreads();

        // scores = (Q @ K^T)*scale with key mask  (SIMT FFMA2)
        if (tid < 500) {
            const int q = tid / 10;
            const int kk0 = (tid % 10) * 5;
            uint64_t acc[5] = {0ull, 0ull, 0ull, 0ull, 0ull};
#pragma unroll 2
            for (int d = 0; d < TD; d += 4) {
                const float4 qa = *(const float4*)(bufA + q * WS + d);
                const uint64_t q01 = pack2(qa.x, qa.y);
                const uint64_t q23 = pack2(qa.z, qa.w);
#pragma unroll
                for (int j = 0; j < 5; j++) {
                    const float4 kv = *(const float4*)(bufB + (kk0 + j) * WS + d);
                    ffma2(acc[j], q01, pack2(kv.x, kv.y));
                    ffma2(acc[j], q23, pack2(kv.z, kv.w));
                }
            }
            const float scale = 0.07071067811865475f;  // 1/sqrt(200)
#pragma unroll
            for (int j = 0; j < 5; j++) {
                float l, h;
                unpack2(acc[j], l, h);
                sS[q * SSTRIDE + kk0 + j] =
                    (km[kk0 + j] != 0.0f) ? NEGV : (l + h) * scale;
            }
        }
        __syncthreads();

        // Softmax rows + query mask
        for (int q = warp; q < TL; q += NTHREADS / 32) {
            const float a  = sS[q * SSTRIDE + lane];
            const float bb = (lane < TL - 32) ? sS[q * SSTRIDE + 32 + lane] : -3.4e38f;
            const float mx = wmax(fmaxf(a, bb));
            const float ea = expf(a - mx);
            const float eb = (lane < TL - 32) ? expf(bb - mx) : 0.0f;
            const float ssum = wsum(ea + eb);
            const float fac = (1.0f - km[q]) / ssum;
            sS[q * SSTRIDE + lane] = ea * fac;
            if (lane < TL - 32) sS[q * SSTRIDE + 32 + lane] = eb * fac;
        }
        __syncthreads();

        // x += attn @ V  (SIMT FFMA2)
        if (tid < 500) {
            const int cg = tid % 50, rg = tid / 50;
            const int n0 = cg * 4, mr = rg * 5;
            uint64_t acc[5][2];
#pragma unroll
            for (int i = 0; i < 5; i++) { acc[i][0] = 0ull; acc[i][1] = 0ull; }
#pragma unroll 2
            for (int kk = 0; kk < TL; kk++) {
                const float4 v = *(const float4*)(bufV + kk * WS + n0);
                const uint64_t v01 = pack2(v.x, v.y);
                const uint64_t v23 = pack2(v.z, v.w);
#pragma unroll
                for (int i = 0; i < 5; i++) {
                    const uint64_t a = rep2(sS[(mr + i) * SSTRIDE + kk]);
                    ffma2(acc[i][0], a, v01);
                    ffma2(acc[i][1], a, v23);
                }
            }
#pragma unroll
            for (int i = 0; i < 5; i++) {
                float a0, a1, a2, a3;
                unpack2(acc[i][0], a0, a1);
                unpack2(acc[i][1], a2, a3);
                float* o = sx + (mr + i) * WS + n0;
                o[0] += a0; o[1] += a1; o[2] += a2; o[3] += a3;
            }
        }
        __syncthreads();

        // FFN1: h1 = relu(x @ W1 + b1) -> bufA
        convert_A(sx, smem, tid);
        __syncthreads();
        gemm_mma(wh1, wl1, b1_, bufA, true, smem, smem_u32, tid);
        __syncthreads();

        // FFN2: h2 = h1 @ W2 + b2 -> bufB
        convert_A(bufA, smem, tid);
        __syncthreads();
        gemm_mma(wh2, wl2, b2_, bufB, false, smem, smem_u32, tid);
        __syncthreads();

        // LayerNorm(h2)*g + be, residual into sx
        for (int r = warp; r < TL; r += NTHREADS / 32) {
            float hbuf[7];
            int nc = 0;
            float s = 0.0f;
            for (int c = lane; c < TD; c += 32) {
                const float h = bufB[r * WS + c];
                hbuf[nc++] = h;
                s += h;
            }
            s = wsum(s);
            const float mu = s * (1.0f / TD);
            float v = 0.0f;
            for (int i = 0; i < nc; i++) {
                const float dd = hbuf[i] - mu;
                v = fmaf(dd, dd, v);
            }
            v = wsum(v);
            const float inv = rsqrtf(v * (1.0f / TD) + LNEPS);
            nc = 0;
            for (int c = lane; c < TD; c += 32) {
                const float y = (hbuf[nc++] - mu) * inv * __ldg(g_ + c) + __ldg(be_ + c);
                sx[r * WS + c] += y;
            }
        }
        __syncthreads();
    }

    // Write out (dense 200 stride)
    {
        float4* o = (float4*)(out + (size_t)b * TL * TD);
        for (int idx = tid; idx < TL * (TD / 4); idx += NTHREADS) {
            const int m = idx / (TD / 4);
            const int c = idx - m * (TD / 4);
            o[idx] = *(const float4*)(sx + m * WS + c * 4);
        }
    }
}

extern "C" void kernel_launch(void* const* d_in, const int* in_sizes, int n_in,
                              void* d_out, int out_size) {
    const int*   tokens = (const int*)d_in[0];
    const float* emb = (const float*)d_in[1];
    const float* Wq  = (const float*)d_in[2];
    const float* bq  = (const float*)d_in[3];
    const float* Wk  = (const float*)d_in[4];
    const float* bk  = (const float*)d_in[5];
    const float* Wv  = (const float*)d_in[6];
    const float* bv  = (const float*)d_in[7];
    const float* W1  = (const float*)d_in[8];
    const float* b1  = (const float*)d_in[9];
    const float* W2  = (const float*)d_in[10];
    const float* b2  = (const float*)d_in[11];
    const float* lng = (const float*)d_in[12];
    const float* lnb = (const float*)d_in[13];
    float* out = (float*)d_out;

    const int B = in_sizes[0] / TL;

    dim3 pgrid(15, TD, 1);
    prep_kernel<<<pgrid, 256>>>(Wq, Wk, Wv, W1, W2);

    cudaFuncSetAttribute(encoder_kernel,
                         cudaFuncAttributeMaxDynamicSharedMemorySize, SM_TOTAL);
    encoder_kernel<<<B, NTHREADS, SM_TOTAL>>>(tokens, emb, bq, bk, bv, b1, b2,
                                              lng, lnb, out);
}

// round 10
// speedup vs baseline: 2.8859x; 1.2623x over previous
#include <cuda_runtime.h>
#include <cuda_bf16.h>
#include <math.h>
#include <stdint.h>

#define TL 50
#define TD 200
#define KSPAD 216         // A row stride in SMEM (bf16) -> 432B, ldsm conflict-free
#define NBLK 3
#define NTHREADS 512
#define WS 204
#define SSTRIDE 52
#define NEGV (-4294967296.0f)
#define LNEPS 1e-8f
#define KSTEPS 13         // 13 x k16 = 208
#define NTILES 25         // 25 x n8 = 200
#define MATSTRIDE (NTILES * KSTEPS * 32)   // uint4 per weight matrix

// SMEM byte offsets
#define SM_AHI 0
#define SM_ALO 27648                    // 64*216*2
#define SM_SX  55296
#define SM_A   (SM_SX + 40800)          // 96096
#define SM_B   (SM_A + 40800)           // 136896
#define SM_V   (SM_B + 40800)           // 177696
#define SM_SS  (SM_V + 40800)           // 218496
#define SM_KM  (SM_SS + 10400)          // 228896
#define SM_TOTAL (SM_KM + 256)          // 229152

// Fragment-packed weights: [mat(15)][nt(25)][ks(13)][lane(32)] = {bh0,bh1,bl0,bl1}
__device__ uint4 g_wfrag[15 * MATSTRIDE];

// ---------------- SIMT helpers ----------------
__device__ __forceinline__ float wsum(float v) {
#pragma unroll
    for (int o = 16; o > 0; o >>= 1) v += __shfl_xor_sync(0xffffffffu, v, o);
    return v;
}
__device__ __forceinline__ float wmax(float v) {
#pragma unroll
    for (int o = 16; o > 0; o >>= 1) v = fmaxf(v, __shfl_xor_sync(0xffffffffu, v, o));
    return v;
}
__device__ __forceinline__ void ffma2(uint64_t& acc, uint64_t a, uint64_t b) {
    asm("fma.rn.f32x2 %0, %1, %2, %0;" : "+l"(acc) : "l"(a), "l"(b));
}
__device__ __forceinline__ uint64_t rep2(float x) {
    uint64_t r; asm("mov.b64 %0, {%1, %1};" : "=l"(r) : "f"(x)); return r;
}
__device__ __forceinline__ uint64_t pack2(float lo, float hi) {
    uint64_t r; asm("mov.b64 %0, {%1, %2};" : "=l"(r) : "f"(lo), "f"(hi)); return r;
}
__device__ __forceinline__ void unpack2(uint64_t v, float& lo, float& hi) {
    asm("mov.b64 {%0, %1}, %2;" : "=f"(lo), "=f"(hi) : "l"(v));
}

// ---------------- MMA helpers ----------------
__device__ __forceinline__ void ldsm_x4(uint32_t r[4], uint32_t addr) {
    asm volatile("ldmatrix.sync.aligned.m8n8.x4.shared.b16 {%0,%1,%2,%3}, [%4];"
                 : "=r"(r[0]), "=r"(r[1]), "=r"(r[2]), "=r"(r[3]) : "r"(addr));
}
__device__ __forceinline__ void mma16816(float c[4], const uint32_t a[4],
                                         uint32_t b0, uint32_t b1) {
    asm volatile(
        "mma.sync.aligned.m16n8k16.row.col.f32.bf16.bf16.f32 "
        "{%0,%1,%2,%3}, {%4,%5,%6,%7}, {%8,%9}, {%0,%1,%2,%3};"
        : "+f"(c[0]), "+f"(c[1]), "+f"(c[2]), "+f"(c[3])
        : "r"(a[0]), "r"(a[1]), "r"(a[2]), "r"(a[3]), "r"(b0), "r"(b1));
}
__device__ __forceinline__ uint32_t cvt_bf16x2(float hi, float lo) {
    uint32_t h;
    asm("cvt.rn.satfinite.bf16x2.f32 %0, %1, %2;" : "=r"(h) : "f"(hi), "f"(lo));
    return h;
}

// ---------------- prep kernel: W[k][n] f32 -> fragment-packed bf16 hi/lo ----------------
// grid (15, 25), 416 threads (13 warps: warp = ks)
__global__ void prep_kernel(const float* __restrict__ Wq, const float* __restrict__ Wk,
                            const float* __restrict__ Wv, const float* __restrict__ W1,
                            const float* __restrict__ W2) {
    const int mat = blockIdx.x;       // 0..14
    const int nt = blockIdx.y;        // 0..24
    const int blk = mat / 5, wh = mat % 5;
    const float* W = (wh == 0 ? Wq : wh == 1 ? Wk : wh == 2 ? Wv : wh == 3 ? W1 : W2)
                     + blk * TD * TD;
    const int ks = threadIdx.x >> 5;  // 0..12
    const int lane = threadIdx.x & 31;
    const int gid = lane >> 2, tig = lane & 3;
    const int n = nt * 8 + gid;
    const int k0 = ks * 16 + 2 * tig;

    auto rd = [&](int k) -> float { return (k < TD) ? __ldg(W + k * TD + n) : 0.0f; };
    const float v0 = rd(k0),     v1 = rd(k0 + 1);
    const float v2 = rd(k0 + 8), v3 = rd(k0 + 9);

    const uint32_t bh0 = cvt_bf16x2(v1, v0);
    const uint32_t bh1 = cvt_bf16x2(v3, v2);
    const float h0 = __uint_as_float(bh0 << 16), h1 = __uint_as_float(bh0 & 0xffff0000u);
    const float h2 = __uint_as_float(bh1 << 16), h3 = __uint_as_float(bh1 & 0xffff0000u);
    const uint32_t bl0 = cvt_bf16x2(v1 - h1, v0 - h0);
    const uint32_t bl1 = cvt_bf16x2(v3 - h3, v2 - h2);

    g_wfrag[(size_t)mat * MATSTRIDE + (nt * KSTEPS + ks) * 32 + lane] =
        make_uint4(bh0, bh1, bl0, bl1);
}

// ---------------- convert A: f32 (stride WS) -> bf16 hi/lo SMEM [64][KSPAD] ----------------
__device__ __forceinline__ void convert_A(const float* __restrict__ src,
                                          char* smem, int tid) {
    __nv_bfloat16* hi = (__nv_bfloat16*)(smem + SM_AHI);
    __nv_bfloat16* lo = (__nv_bfloat16*)(smem + SM_ALO);
    for (int idx = tid; idx < TL * (TD / 2); idx += NTHREADS) {
        const int row = idx / (TD / 2);
        const int c2 = (idx - row * (TD / 2)) * 2;
        const float x0 = src[row * WS + c2];
        const float x1 = src[row * WS + c2 + 1];
        const uint32_t h = cvt_bf16x2(x1, x0);
        const float h0 = __uint_as_float(h << 16);
        const float h1 = __uint_as_float(h & 0xffff0000u);
        const uint32_t l = cvt_bf16x2(x1 - h1, x0 - h0);
        *(uint32_t*)(hi + row * KSPAD + c2) = h;
        *(uint32_t*)(lo + row * KSPAD + c2) = l;
    }
}

// ---------------- fused tensor-core GEMM over NM weight matrices ----------------
// A: SMEM bf16 hi/lo [64][KSPAD]; B: g_wfrag fragments (consecutive mats from fb).
// 16 warps; warp w owns n8-tiles {w, w+16}.
template<int NM, bool RELU>
__device__ __forceinline__ void gemm_mma_f(
    const uint4* __restrict__ fb,
    float* const* dsts, const float* const* biases,
    uint32_t smem_u32, int tid)
{
    const int w = tid >> 5, lane = tid & 31;
    const int gid = lane >> 2, tig = lane & 3;
    const uint32_t abase = smem_u32 + ((uint32_t)((lane & 15) * KSPAD + (lane >> 4) * 8)) * 2u;

#pragma unroll 1
    for (int nt = w; nt < NTILES; nt += 16) {
        float c[NM][4][4];
#pragma unroll
        for (int m = 0; m < NM; m++)
#pragma unroll
            for (int mt = 0; mt < 4; mt++)
#pragma unroll
                for (int j = 0; j < 4; j++) c[m][mt][j] = 0.0f;

        const uint4* fr = fb + nt * (KSTEPS * 32) + lane;

#pragma unroll 1
        for (int ks = 0; ks < KSTEPS; ks++) {
            uint4 bf[NM];
#pragma unroll
            for (int m = 0; m < NM; m++)
                bf[m] = __ldg(fr + (size_t)m * MATSTRIDE + ks * 32);
            const uint32_t koff = (uint32_t)(ks * 32);
#pragma unroll
            for (int mt = 0; mt < 4; mt++) {
                uint32_t ah[4], al[4];
                const uint32_t aoff = (uint32_t)(mt * 16 * KSPAD * 2) + koff;
                ldsm_x4(ah, abase + SM_AHI + aoff);
                ldsm_x4(al, abase + SM_ALO + aoff);
#pragma unroll
                for (int m = 0; m < NM; m++) {
                    mma16816(c[m][mt], ah, bf[m].x, bf[m].y);
                    mma16816(c[m][mt], al, bf[m].x, bf[m].y);
                    mma16816(c[m][mt], ah, bf[m].z, bf[m].w);
                }
            }
        }

        const int col0 = nt * 8 + 2 * tig;
#pragma unroll
        for (int m = 0; m < NM; m++) {
            const float bx = __ldg(biases[m] + col0);
            const float by = __ldg(biases[m] + col0 + 1);
            float* dst = dsts[m];
#pragma unroll
            for (int mt = 0; mt < 4; mt++) {
                const int r0 = mt * 16 + gid;
                if (r0 < TL) {
                    float v0 = c[m][mt][0] + bx, v1 = c[m][mt][1] + by;
                    if (RELU) { v0 = fmaxf(v0, 0.0f); v1 = fmaxf(v1, 0.0f); }
                    dst[r0 * WS + col0] = v0;
                    dst[r0 * WS + col0 + 1] = v1;
                }
                const int r1 = mt * 16 + gid + 8;
                if (r1 < TL) {
                    float v2 = c[m][mt][2] + bx, v3 = c[m][mt][3] + by;
                    if (RELU) { v2 = fmaxf(v2, 0.0f); v3 = fmaxf(v3, 0.0f); }
                    dst[r1 * WS + col0] = v2;
                    dst[r1 * WS + col0 + 1] = v3;
                }
            }
        }
    }
}

// ---------------- main kernel ----------------
__global__ void __launch_bounds__(NTHREADS, 1) encoder_kernel(
    const int* __restrict__ tokens, const float* __restrict__ emb,
    const float* __restrict__ bq, const float* __restrict__ bk,
    const float* __restrict__ bv, const float* __restrict__ b1,
    const float* __restrict__ b2,
    const float* __restrict__ lng, const float* __restrict__ lnb,
    float* __restrict__ out)
{
    extern __shared__ char smem[];
    const uint32_t smem_u32 = (uint32_t)__cvta_generic_to_shared(smem);
    float* sx   = (float*)(smem + SM_SX);
    float* bufA = (float*)(smem + SM_A);
    float* bufB = (float*)(smem + SM_B);
    float* bufV = (float*)(smem + SM_V);
    float* sS   = (float*)(smem + SM_SS);
    float* km   = (float*)(smem + SM_KM);

    const int tid = threadIdx.x;
    const int b = blockIdx.x;
    const int warp = tid >> 5, lane = tid & 31;

    // zero A bf16 buffers (padding rows/cols stay zero forever)
    {
        uint32_t* az = (uint32_t*)(smem + SM_AHI);
        for (int i = tid; i < (2 * 64 * KSPAD) / 2; i += NTHREADS) az[i] = 0u;
    }
    // Embedding gather: sx = emb[tokens[b]]  (stride WS)
    {
        const int* tok = tokens + b * TL;
        for (int idx = tid; idx < TL * (TD / 4); idx += NTHREADS) {
            const int m = idx / (TD / 4);
            const int c = idx - m * (TD / 4);
            const int t = __ldg(tok + m);
            *(float4*)(sx + m * WS + c * 4) =
                __ldg((const float4*)emb + (size_t)t * (TD / 4) + c);
        }
    }
    __syncthreads();

    for (int blk = 0; blk < NBLK; blk++) {
        const int m0 = blk * 5;
        const float* bq_ = bq + blk * TD;
        const float* bk_ = bk + blk * TD;
        const float* bv_ = bv + blk * TD;
        const float* b1_ = b1 + blk * TD;
        const float* b2_ = b2 + blk * TD;
        const float* g_  = lng + blk * TD;
        const float* be_ = lnb + blk * TD;

        // Row masks: km[r] = 1 if sum(x[r,:]) == 0
        for (int r = warp; r < TL; r += NTHREADS / 32) {
            float s = 0.0f;
            for (int c = lane; c < TD; c += 32) s += sx[r * WS + c];
            s = wsum(s);
            if (lane == 0) km[r] = (s == 0.0f) ? 1.0f : 0.0f;
        }
        convert_A(sx, smem, tid);
        __syncthreads();

        // Fused Q|K|V on tensor cores
        {
            float* dsts[3] = {bufA, bufB, bufV};
            const float* biases[3] = {bq_, bk_, bv_};
            gemm_mma_f<3, true>(g_wfrag + (size_t)m0 * MATSTRIDE, dsts, biases,
                                smem_u32, tid);
        }
        __syncthreads();

        // scores = (Q @ K^T)*scale with key mask  (SIMT FFMA2)
        if (tid < 500) {
            const int q = tid / 10;
            const int kk0 = (tid % 10) * 5;
            uint64_t acc[5] = {0ull, 0ull, 0ull, 0ull, 0ull};
#pragma unroll 2
            for (int d = 0; d < TD; d += 4) {
                const float4 qa = *(const float4*)(bufA + q * WS + d);
                const uint64_t q01 = pack2(qa.x, qa.y);
                const uint64_t q23 = pack2(qa.z, qa.w);
#pragma unroll
                for (int j = 0; j < 5; j++) {
                    const float4 kv = *(const float4*)(bufB + (kk0 + j) * WS + d);
                    ffma2(acc[j], q01, pack2(kv.x, kv.y));
                    ffma2(acc[j], q23, pack2(kv.z, kv.w));
                }
            }
            const float scale = 0.07071067811865475f;  // 1/sqrt(200)
#pragma unroll
            for (int j = 0; j < 5; j++) {
                float l, h;
                unpack2(acc[j], l, h);
                sS[q * SSTRIDE + kk0 + j] =
                    (km[kk0 + j] != 0.0f) ? NEGV : (l + h) * scale;
            }
        }
        __syncthreads();

        // Softmax rows + query mask
        for (int q = warp; q < TL; q += NTHREADS / 32) {
            const float a  = sS[q * SSTRIDE + lane];
            const float bb = (lane < TL - 32) ? sS[q * SSTRIDE + 32 + lane] : -3.4e38f;
            const float mx = wmax(fmaxf(a, bb));
            const float ea = expf(a - mx);
            const float eb = (lane < TL - 32) ? expf(bb - mx) : 0.0f;
            const float ssum = wsum(ea + eb);
            const float fac = (1.0f - km[q]) / ssum;
            sS[q * SSTRIDE + lane] = ea * fac;
            if (lane < TL - 32) sS[q * SSTRIDE + 32 + lane] = eb * fac;
        }
        __syncthreads();

        // x += attn @ V  (SIMT FFMA2)
        if (tid < 500) {
            const int cg = tid % 50, rg = tid / 50;
            const int n0 = cg * 4, mr = rg * 5;
            uint64_t acc[5][2];
#pragma unroll
            for (int i = 0; i < 5; i++) { acc[i][0] = 0ull; acc[i][1] = 0ull; }
#pragma unroll 2
            for (int kk = 0; kk < TL; kk++) {
                const float4 v = *(const float4*)(bufV + kk * WS + n0);
                const uint64_t v01 = pack2(v.x, v.y);
                const uint64_t v23 = pack2(v.z, v.w);
#pragma unroll
                for (int i = 0; i < 5; i++) {
                    const uint64_t a = rep2(sS[(mr + i) * SSTRIDE + kk]);
                    ffma2(acc[i][0], a, v01);
                    ffma2(acc[i][1], a, v23);
                }
            }
#pragma unroll
            for (int i = 0; i < 5; i++) {
                float a0, a1, a2, a3;
                unpack2(acc[i][0], a0, a1);
                unpack2(acc[i][1], a2, a3);
                float* o = sx + (mr + i) * WS + n0;
                o[0] += a0; o[1] += a1; o[2] += a2; o[3] += a3;
            }
        }
        __syncthreads();

        // FFN1: h1 = relu(x @ W1 + b1) -> bufA
        convert_A(sx, smem, tid);
        __syncthreads();
        {
            float* dsts[1] = {bufA};
            const float* biases[1] = {b1_};
            gemm_mma_f<1, true>(g_wfrag + (size_t)(m0 + 3) * MATSTRIDE, dsts, biases,
                                smem_u32, tid);
        }
        __syncthreads();

        // FFN2: h2 = h1 @ W2 + b2 -> bufB
        convert_A(bufA, smem, tid);
        __syncthreads();
        {
            float* dsts[1] = {bufB};
            const float* biases[1] = {b2_};
            gemm_mma_f<1, false>(g_wfrag + (size_t)(m0 + 4) * MATSTRIDE, dsts, biases,
                                 smem_u32, tid);
        }
        __syncthreads();

        // LayerNorm(h2)*g + be, residual into sx
        for (int r = warp; r < TL; r += NTHREADS / 32) {
            float hbuf[7];
            int nc = 0;
            float s = 0.0f;
            for (int c = lane; c < TD; c += 32) {
                const float h = bufB[r * WS + c];
                hbuf[nc++] = h;
                s += h;
            }
            s = wsum(s);
            const float mu = s * (1.0f / TD);
            float v = 0.0f;
            for (int i = 0; i < nc; i++) {
                const float dd = hbuf[i] - mu;
                v = fmaf(dd, dd, v);
            }
            v = wsum(v);
            const float inv = rsqrtf(v * (1.0f / TD) + LNEPS);
            nc = 0;
            for (int c = lane; c < TD; c += 32) {
                const float y = (hbuf[nc++] - mu) * inv * __ldg(g_ + c) + __ldg(be_ + c);
                sx[r * WS + c] += y;
            }
        }
        __syncthreads();
    }

    // Write out (dense 200 stride)
    {
        float4* o = (float4*)(out + (size_t)b * TL * TD);
        for (int idx = tid; idx < TL * (TD / 4); idx += NTHREADS) {
            const int m = idx / (TD / 4);
            const int c = idx - m * (TD / 4);
            o[idx] = *(const float4*)(sx + m * WS + c * 4);
        }
    }
}

extern "C" void kernel_launch(void* const* d_in, const int* in_sizes, int n_in,
                              void* d_out, int out_size) {
    const int*   tokens = (const int*)d_in[0];
    const float* emb = (const float*)d_in[1];
    const float* Wq  = (const float*)d_in[2];
    const float* bq  = (const float*)d_in[3];
    const float* Wk  = (const float*)d_in[4];
    const float* bk  = (const float*)d_in[5];
    const float* Wv  = (const float*)d_in[6];
    const float* bv  = (const float*)d_in[7];
    const float* W1  = (const float*)d_in[8];
    const float* b1  = (const float*)d_in[9];
    const float* W2  = (const float*)d_in[10];
    const float* b2  = (const float*)d_in[11];
    const float* lng = (const float*)d_in[12];
    const float* lnb = (const float*)d_in[13];
    float* out = (float*)d_out;

    const int B = in_sizes[0] / TL;

    dim3 pgrid(15, NTILES, 1);
    prep_kernel<<<pgrid, 13 * 32>>>(Wq, Wk, Wv, W1, W2);

    cudaFuncSetAttribute(encoder_kernel,
                         cudaFuncAttributeMaxDynamicSharedMemorySize, SM_TOTAL);
    encoder_kernel<<<B, NTHREADS, SM_TOTAL>>>(tokens, emb, bq, bk, bv, b1, b2,
                                              lng, lnb, out);
}